// round 6
// baseline (speedup 1.0000x reference)
#include <cuda_runtime.h>
#include <cuda_bf16.h>

// Problem: B=8192, C = N*D = 2048, K = 1024
#define C_DIM 2048
#define K_DIM 1024
#define B_MAX 8192

// ---------------- device scratch ----------------
__device__ __nv_bfloat16 g_zb[(size_t)B_MAX * C_DIM];   // 32 MB
__device__ __nv_bfloat16 g_wb[(size_t)K_DIM * C_DIM];   // 4 MB
__device__ float g_scores[(size_t)B_MAX * K_DIM];       // 32 MB
__device__ float g_whalf[K_DIM];
__device__ int   g_ind[B_MAX];
__device__ float g_loss;

__global__ void zero_k() { g_loss = 0.0f; }

// ---------------- fp32 -> bf16 convert ----------------
__global__ void cvt_k(const float* __restrict__ src, __nv_bfloat16* __restrict__ dst, int n4) {
    int i = blockIdx.x * blockDim.x + threadIdx.x;
    int stride = gridDim.x * blockDim.x;
    for (; i < n4; i += stride) {
        float4 v = ((const float4*)src)[i];
        __nv_bfloat162 a = __floats2bfloat162_rn(v.x, v.y);
        __nv_bfloat162 b = __floats2bfloat162_rn(v.z, v.w);
        uint2 u;
        u.x = *(unsigned*)&a;
        u.y = *(unsigned*)&b;
        ((uint2*)dst)[i] = u;
    }
}

// ---------------- 0.5*||w_k||^2 (exact fp32) ----------------
__global__ void wnorm_k(const float* __restrict__ w) {
    int k = blockIdx.x;
    float s = 0.0f;
    const float4* wr = (const float4*)(w + (size_t)k * C_DIM);
    for (int c = threadIdx.x; c < C_DIM / 4; c += 256) {
        float4 v = wr[c];
        s += v.x * v.x + v.y * v.y + v.z * v.z + v.w * v.w;
    }
    __shared__ float red[256];
    red[threadIdx.x] = s;
    __syncthreads();
    for (int o = 128; o > 0; o >>= 1) {
        if (threadIdx.x < o) red[threadIdx.x] += red[threadIdx.x + o];
        __syncthreads();
    }
    if (threadIdx.x == 0) g_whalf[k] = 0.5f * red[0];
}

// ---------------- mma.sync bf16 GEMM: scores = zb . wb^T ----------------
// BM=128, BN=128, BK=64(bf16), 3-stage cp.async, 8 warps, warp tile 32x64.
#define BM 128
#define BN 128
#define BKB 128           // BK in bytes: 64 bf16 = 128 B (one SW128 row)
#define STAGES 3
#define A_ST (BM * BKB)   // 16384 B
#define B_ST (BN * BKB)   // 16384 B
#define GSMEM (STAGES * (A_ST + B_ST) + 1024)

#define SWZ128(off) ((off) ^ (((off) >> 3) & 0x70))

__device__ __forceinline__ unsigned smem_u32(const void* p) {
    unsigned a;
    asm("{ .reg .u64 t; cvta.to.shared.u64 t, %1; cvt.u32.u64 %0, t; }" : "=r"(a) : "l"(p));
    return a;
}
__device__ __forceinline__ void cp16(unsigned s, const void* g) {
    asm volatile("cp.async.cg.shared.global [%0], [%1], 16;" :: "r"(s), "l"(g));
}
__device__ __forceinline__ void ldm4(unsigned* d, unsigned addr) {
    asm volatile("ldmatrix.sync.aligned.m8n8.x4.shared.b16 {%0,%1,%2,%3}, [%4];"
                 : "=r"(d[0]), "=r"(d[1]), "=r"(d[2]), "=r"(d[3]) : "r"(addr));
}
__device__ __forceinline__ void mma16816(float* c, const unsigned* a, unsigned b0, unsigned b1) {
    asm volatile(
        "mma.sync.aligned.m16n8k16.row.col.f32.bf16.bf16.f32 "
        "{%0,%1,%2,%3}, {%4,%5,%6,%7}, {%8,%9}, {%0,%1,%2,%3};"
        : "+f"(c[0]), "+f"(c[1]), "+f"(c[2]), "+f"(c[3])
        : "r"(a[0]), "r"(a[1]), "r"(a[2]), "r"(a[3]), "r"(b0), "r"(b1));
}

__global__ __launch_bounds__(256, 2) void gemm_k(
    const __nv_bfloat16* __restrict__ zb,
    const __nv_bfloat16* __restrict__ wb,
    float* __restrict__ scores)
{
    extern __shared__ char dsm[];
    unsigned base = (smem_u32(dsm) + 1023u) & ~1023u;
    const unsigned aB = base;                 // 3 stages A
    const unsigned bB = base + STAGES * A_ST; // 3 stages B

    const int tid = threadIdx.x;
    const int wid = tid >> 5;
    const int lane = tid & 31;
    const int wm = wid & 3;       // warp M: 0..3  -> rows wm*32
    const int wn = wid >> 2;      // warp N: 0..1  -> cols wn*64

    const __nv_bfloat16* zrow = zb + (size_t)(blockIdx.x * BM) * C_DIM;
    const __nv_bfloat16* wrow = wb + (size_t)(blockIdx.y * BN) * C_DIM;

    // loader: 16B per thread; A/B each 4 rounds of 256 threads
    const int lr = tid >> 3;          // 0..31 row step
    const int lc = (tid & 7) * 16;    // byte col 0..112

    float acc[2][8][4];
#pragma unroll
    for (int i = 0; i < 2; i++)
#pragma unroll
        for (int j = 0; j < 8; j++)
#pragma unroll
            for (int q = 0; q < 4; q++) acc[i][j][q] = 0.0f;

    const int NIT = C_DIM * 2 / BKB;   // 32 iters (64 bf16 per iter)

    // prefetch stages 0..STAGES-2
#pragma unroll
    for (int s = 0; s < STAGES - 1; s++) {
        int kb = s * BKB;   // byte offset into K
#pragma unroll
        for (int r = 0; r < 4; r++) {
            int row = r * 32 + lr;
            cp16(aB + s * A_ST + SWZ128((unsigned)(row * BKB + lc)),
                 (const char*)(zrow + (size_t)row * C_DIM) + kb + lc);
            cp16(bB + s * B_ST + SWZ128((unsigned)(row * BKB + lc)),
                 (const char*)(wrow + (size_t)row * C_DIM) + kb + lc);
        }
        asm volatile("cp.async.commit_group;");
    }

    for (int i = 0; i < NIT; i++) {
        asm volatile("cp.async.wait_group %0;" :: "n"(STAGES - 2));
        __syncthreads();

        // issue loads for stage i+STAGES-1
        if (i + STAGES - 1 < NIT) {
            int s = (i + STAGES - 1) % STAGES;
            int kb = (i + STAGES - 1) * BKB;
#pragma unroll
            for (int r = 0; r < 4; r++) {
                int row = r * 32 + lr;
                cp16(aB + s * A_ST + SWZ128((unsigned)(row * BKB + lc)),
                     (const char*)(zrow + (size_t)row * C_DIM) + kb + lc);
                cp16(bB + s * B_ST + SWZ128((unsigned)(row * BKB + lc)),
                     (const char*)(wrow + (size_t)row * C_DIM) + kb + lc);
            }
        }
        asm volatile("cp.async.commit_group;");

        // compute from stage i%STAGES
        const unsigned aS = aB + (i % STAGES) * A_ST;
        const unsigned bS = bB + (i % STAGES) * B_ST;
        const int lrow = lane & 15;
        const int lhalf = (lane >> 4) * 16;   // 0 or 16 bytes (k half)

#pragma unroll
        for (int kk = 0; kk < 4; kk++) {       // 4 x k16 per 64-elem chunk
            const int kbyte = kk * 32;
            unsigned af[2][4];
#pragma unroll
            for (int mt = 0; mt < 2; mt++) {
                int row = wm * 32 + mt * 16 + lrow;
                ldm4(af[mt], aS + SWZ128((unsigned)(row * BKB + kbyte + lhalf)));
            }
            unsigned bf[4][4];
#pragma unroll
            for (int nt2 = 0; nt2 < 4; nt2++) {
                int row = wn * 64 + nt2 * 16 + lrow;
                ldm4(bf[nt2], bS + SWZ128((unsigned)(row * BKB + kbyte + lhalf)));
            }
#pragma unroll
            for (int mt = 0; mt < 2; mt++)
#pragma unroll
                for (int nt = 0; nt < 8; nt++) {
                    // n-tile nt: n16 group nt/2, lower/upper half nt%2
                    const unsigned* bv = bf[nt >> 1];
                    unsigned b0 = (nt & 1) ? bv[1] : bv[0];
                    unsigned b1 = (nt & 1) ? bv[3] : bv[2];
                    mma16816(acc[mt][nt], af[mt], b0, b1);
                }
        }
    }

    // epilogue: write scores
    const int r0 = blockIdx.x * BM + wm * 32 + (lane >> 2);
    const int c0 = blockIdx.y * BN + wn * 64 + (lane & 3) * 2;
#pragma unroll
    for (int mt = 0; mt < 2; mt++) {
#pragma unroll
        for (int nt = 0; nt < 8; nt++) {
            float* p = scores + (size_t)(r0 + mt * 16) * K_DIM + c0 + nt * 8;
            *(float2*)p = make_float2(acc[mt][nt][0], acc[mt][nt][1]);
            *(float2*)(p + 8 * K_DIM) = make_float2(acc[mt][nt][2], acc[mt][nt][3]);
        }
    }
}

// ---------------- select: approx argmax + exact fp32 refinement ----------------
#define MARGIN 2.0f
#define MAXCAND 32

__global__ __launch_bounds__(128) void select_k(const float* __restrict__ z,
                                                const float* __restrict__ w)
{
    const int b = blockIdx.x;
    const int t = threadIdx.x;
    const float* srow = g_scores + (size_t)b * K_DIM;

    float sv[8];
    float bv = -3.4e38f;
    int bi = 0;
#pragma unroll
    for (int j = 0; j < 8; j++) {
        int k = j * 128 + t;
        float s = srow[k] - g_whalf[k];
        sv[j] = s;
        if (s > bv || (s == bv && k < bi)) { bv = s; bi = k; }
    }

    __shared__ float rv[128];
    __shared__ int ri[128];
    rv[t] = bv; ri[t] = bi;
    __syncthreads();
    for (int o = 64; o > 0; o >>= 1) {
        if (t < o) {
            float v2 = rv[t + o]; int i2 = ri[t + o];
            if (v2 > rv[t] || (v2 == rv[t] && i2 < ri[t])) { rv[t] = v2; ri[t] = i2; }
        }
        __syncthreads();
    }
    const float bestv = rv[0];
    const int besti = ri[0];

    __shared__ int cnt;
    __shared__ int cand[MAXCAND];
    if (t == 0) cnt = 0;
    __syncthreads();
#pragma unroll
    for (int j = 0; j < 8; j++) {
        int k = j * 128 + t;
        if (k != besti && sv[j] >= bestv - MARGIN) {
            int p = atomicAdd(&cnt, 1);
            if (p < MAXCAND) cand[p] = k;
        }
    }
    __syncthreads();

    int nc = cnt < MAXCAND ? cnt : MAXCAND;
    if (nc == 0) {
        if (t == 0) g_ind[b] = besti;
        return;
    }

    const float* zr = z + (size_t)b * C_DIM;
    __shared__ float part[128];
    float ebv = -3.4e38f;
    int ebi = 0;
    for (int c = -1; c < nc; c++) {
        int k = (c < 0) ? besti : cand[c];
        const float* wr = w + (size_t)k * C_DIM;
        float p = 0.0f;
        for (int d = t; d < C_DIM; d += 128) p += zr[d] * wr[d];
        part[t] = p;
        __syncthreads();
        for (int o = 64; o > 0; o >>= 1) {
            if (t < o) part[t] += part[t + o];
            __syncthreads();
        }
        float s = part[0] - g_whalf[k];
        if (s > ebv || (s == ebv && k < ebi)) { ebv = s; ebi = k; }
        __syncthreads();
    }
    if (t == 0) g_ind[b] = ebi;
}

// ---------------- gather z_q = w[ind], exact sum((w[ind]-z)^2) ----------------
__global__ void gather_k(const float* __restrict__ z, const float* __restrict__ w,
                         float* __restrict__ out)
{
    int b = blockIdx.x;
    int ind = g_ind[b];
    const float4* wr = (const float4*)(w + (size_t)ind * C_DIM);
    const float4* zr = (const float4*)(z + (size_t)b * C_DIM);
    float4* o = (float4*)(out + (size_t)b * C_DIM);

    float s = 0.0f;
    for (int c = threadIdx.x; c < C_DIM / 4; c += 256) {
        float4 wv = wr[c];
        float4 zv = zr[c];
        o[c] = wv;
        float d0 = wv.x - zv.x, d1 = wv.y - zv.y, d2 = wv.z - zv.z, d3 = wv.w - zv.w;
        s += d0 * d0 + d1 * d1 + d2 * d2 + d3 * d3;
    }
    __shared__ float red[256];
    red[threadIdx.x] = s;
    __syncthreads();
    for (int o2 = 128; o2 > 0; o2 >>= 1) {
        if (threadIdx.x < o2) red[threadIdx.x] += red[threadIdx.x + o2];
        __syncthreads();
    }
    if (threadIdx.x == 0) atomicAdd(&g_loss, red[0]);
}

__global__ void fin_k(float* out, int loss_idx, float inv_n) {
    out[loss_idx] = 12.5f * g_loss * inv_n;   // KLD_SCALE*(1+COMMITMENT_COST)*mse
}

extern "C" void kernel_launch(void* const* d_in, const int* in_sizes, int n_in,
                              void* d_out, int out_size)
{
    const float* z = (const float*)d_in[0];
    const float* w = (const float*)d_in[1];
    float* out = (float*)d_out;
    const int B = in_sizes[0] / C_DIM;   // 8192

    void* p_zb; cudaGetSymbolAddress(&p_zb, g_zb);
    void* p_wb; cudaGetSymbolAddress(&p_wb, g_wb);
    void* p_sc; cudaGetSymbolAddress(&p_sc, g_scores);

    cudaFuncSetAttribute(gemm_k, cudaFuncAttributeMaxDynamicSharedMemorySize, GSMEM);

    zero_k<<<1, 1>>>();
    cvt_k<<<2048, 256>>>(z, (__nv_bfloat16*)p_zb, B * C_DIM / 4);
    cvt_k<<<1024, 256>>>(w, (__nv_bfloat16*)p_wb, K_DIM * C_DIM / 4);
    wnorm_k<<<K_DIM, 256>>>(w);

    dim3 ggrid(B / BM, K_DIM / BN);
    gemm_k<<<ggrid, 256, GSMEM>>>((const __nv_bfloat16*)p_zb,
                                  (const __nv_bfloat16*)p_wb,
                                  (float*)p_sc);

    select_k<<<B, 128>>>(z, w);
    gather_k<<<B, 256>>>(z, w, out);
    fin_k<<<1, 1>>>(out, out_size - 1, 1.0f / ((float)B * (float)C_DIM));
}